// round 17
// baseline (speedup 1.0000x reference)
#include <cuda_runtime.h>

#define N    512
#define DIM  384
#define BK   32
#define NTL  12          // DIM / BK
#define TRI  136         // upper-triangle 32x32 tiles of a 512x512 matrix (16*17/2)

// Scratch (device globals per allocation-free rule)
__device__ float    g_D[N * N];    // pairwise distances, diag = 1e6
__device__ float    g_prec[N];     // per-query soft precision
__device__ unsigned g_ctr1;        // monotonic ticket: grid barrier (replay-safe)
__device__ unsigned g_ctr2;        // monotonic ticket: completion count

// Branchless full-range sigmoid (exp underflow -> exact 0/1 saturation)
__device__ __forceinline__ float sigmoid_nb(float x) {
    float e = __expf(-fabsf(x));
    float p = __fdividef(1.f, 1.f + e);
    return (x >= 0.f) ? p : 1.f - p;
}

#define S_STR 36    // 144 B rows: 16B-aligned
// phase1: sa 2*32*36 + sb 2*32*36 = 4608 floats (18.4 KB)
// phase2 aliases: sd 4*512 = 2048 | slab 512 = 2560 floats
#define SMEM_FLOATS (4 * BK * S_STR)

__global__ void __launch_bounds__(512, 1)
k_fused(const float* __restrict__ emb, const int* __restrict__ labels,
        float* __restrict__ out)
{
    __shared__ __align__(16) float smem[SMEM_FLOATS];
    __shared__ float snA[32];
    __shared__ float snB[32];
    __shared__ float wnum[16];
    __shared__ int   wcnt[16];
    __shared__ float swr[16];
    __shared__ int   s_done;

    const int t = threadIdx.x;
    const int b = blockIdx.x;

    // triangular tile map: b -> (ti, tj), ti <= tj
    int ti = 0, rem = b;
#pragma unroll 1
    while (rem >= 16 - ti) { rem -= 16 - ti; ti++; }
    const int tj = ti + rem;
    const int q0 = ti * 32;
    const int m0 = tj * 32;

    // ======== Phase 1: symmetric Gram -> distance tile 32x32, t<128 active ========
    {
        float* sa = smem;                     // [2][BK*S_STR]  q-side
        float* sb = smem + 2 * BK * S_STR;    // [2][BK*S_STR]  m-side

        const bool act = (t < 128);
        const int  ty  = t >> 3;       // 0..15 -> q-rows 2ty, 2ty+1
        const int  tx  = t & 7;        // 0..7  -> m-cols 4tx..+3
        const int  arow = t >> 3, ac4 = t & 7;   // loader decomposition (same split)

        const float* pa0 = emb + (size_t)(q0 + arow)      * DIM + ac4 * 4;
        const float* pa1 = emb + (size_t)(q0 + arow + 16) * DIM + ac4 * 4;
        const float* pb0 = emb + (size_t)(m0 + arow)      * DIM + ac4 * 4;
        const float* pb1 = emb + (size_t)(m0 + arow + 16) * DIM + ac4 * 4;

        float acc[2][4] = {{0.f,0.f,0.f,0.f},{0.f,0.f,0.f,0.f}};
        float nA0 = 0.f, nA1 = 0.f, nB0 = 0.f, nB1 = 0.f;
        float4 ra0 = {0,0,0,0}, ra1 = {0,0,0,0}, rb0 = {0,0,0,0}, rb1 = {0,0,0,0};

        if (act) {
            ra0 = *(const float4*)pa0;  ra1 = *(const float4*)pa1;
            rb0 = *(const float4*)pb0;  rb1 = *(const float4*)pb1;
#pragma unroll
            for (int e = 0; e < 4; e++) {
                sa[(ac4 * 4 + e) * S_STR + arow]      = ((const float*)&ra0)[e];
                sa[(ac4 * 4 + e) * S_STR + arow + 16] = ((const float*)&ra1)[e];
                sb[(ac4 * 4 + e) * S_STR + arow]      = ((const float*)&rb0)[e];
                sb[(ac4 * 4 + e) * S_STR + arow + 16] = ((const float*)&rb1)[e];
            }
            nA0 = fmaf(ra0.x,ra0.x,fmaf(ra0.y,ra0.y,fmaf(ra0.z,ra0.z,fmaf(ra0.w,ra0.w,nA0))));
            nA1 = fmaf(ra1.x,ra1.x,fmaf(ra1.y,ra1.y,fmaf(ra1.z,ra1.z,fmaf(ra1.w,ra1.w,nA1))));
            nB0 = fmaf(rb0.x,rb0.x,fmaf(rb0.y,rb0.y,fmaf(rb0.z,rb0.z,fmaf(rb0.w,rb0.w,nB0))));
            nB1 = fmaf(rb1.x,rb1.x,fmaf(rb1.y,rb1.y,fmaf(rb1.z,rb1.z,fmaf(rb1.w,rb1.w,nB1))));
        }
        __syncthreads();

#pragma unroll 1
        for (int tt = 0; tt < NTL; tt++) {
            const int cur = tt & 1;
            if (act) {
                if (tt + 1 < NTL) {   // prefetch next tile into registers
                    const int ko = (tt + 1) * BK;
                    ra0 = *(const float4*)(pa0 + ko);
                    ra1 = *(const float4*)(pa1 + ko);
                    rb0 = *(const float4*)(pb0 + ko);
                    rb1 = *(const float4*)(pb1 + ko);
                }
                const float* csa = sa + cur * BK * S_STR;
                const float* csb = sb + cur * BK * S_STR;
#pragma unroll
                for (int k = 0; k < BK; k++) {
                    float2 av = *(const float2*)&csa[k * S_STR + 2 * ty];
                    float4 bv = *(const float4*)&csb[k * S_STR + 4 * tx];
                    acc[0][0] = fmaf(av.x, bv.x, acc[0][0]);
                    acc[0][1] = fmaf(av.x, bv.y, acc[0][1]);
                    acc[0][2] = fmaf(av.x, bv.z, acc[0][2]);
                    acc[0][3] = fmaf(av.x, bv.w, acc[0][3]);
                    acc[1][0] = fmaf(av.y, bv.x, acc[1][0]);
                    acc[1][1] = fmaf(av.y, bv.y, acc[1][1]);
                    acc[1][2] = fmaf(av.y, bv.z, acc[1][2]);
                    acc[1][3] = fmaf(av.y, bv.w, acc[1][3]);
                }
                if (tt + 1 < NTL) {   // store prefetched tile into the other buffer
                    float* nsa = sa + (cur ^ 1) * BK * S_STR;
                    float* nsb = sb + (cur ^ 1) * BK * S_STR;
#pragma unroll
                    for (int e = 0; e < 4; e++) {
                        nsa[(ac4 * 4 + e) * S_STR + arow]      = ((const float*)&ra0)[e];
                        nsa[(ac4 * 4 + e) * S_STR + arow + 16] = ((const float*)&ra1)[e];
                        nsb[(ac4 * 4 + e) * S_STR + arow]      = ((const float*)&rb0)[e];
                        nsb[(ac4 * 4 + e) * S_STR + arow + 16] = ((const float*)&rb1)[e];
                    }
                    nA0 = fmaf(ra0.x,ra0.x,fmaf(ra0.y,ra0.y,fmaf(ra0.z,ra0.z,fmaf(ra0.w,ra0.w,nA0))));
                    nA1 = fmaf(ra1.x,ra1.x,fmaf(ra1.y,ra1.y,fmaf(ra1.z,ra1.z,fmaf(ra1.w,ra1.w,nA1))));
                    nB0 = fmaf(rb0.x,rb0.x,fmaf(rb0.y,rb0.y,fmaf(rb0.z,rb0.z,fmaf(rb0.w,rb0.w,nB0))));
                    nB1 = fmaf(rb1.x,rb1.x,fmaf(rb1.y,rb1.y,fmaf(rb1.z,rb1.z,fmaf(rb1.w,rb1.w,nB1))));
                }
            }
            if (tt + 1 < NTL) __syncthreads();   // uniform condition
        }

        if (act) {
            // 8 k-chunk threads per row share t>>3 -> xor 1,2,4 in-warp
            nA0 += __shfl_xor_sync(0xffffffffu, nA0, 1);
            nA0 += __shfl_xor_sync(0xffffffffu, nA0, 2);
            nA0 += __shfl_xor_sync(0xffffffffu, nA0, 4);
            nA1 += __shfl_xor_sync(0xffffffffu, nA1, 1);
            nA1 += __shfl_xor_sync(0xffffffffu, nA1, 2);
            nA1 += __shfl_xor_sync(0xffffffffu, nA1, 4);
            nB0 += __shfl_xor_sync(0xffffffffu, nB0, 1);
            nB0 += __shfl_xor_sync(0xffffffffu, nB0, 2);
            nB0 += __shfl_xor_sync(0xffffffffu, nB0, 4);
            nB1 += __shfl_xor_sync(0xffffffffu, nB1, 1);
            nB1 += __shfl_xor_sync(0xffffffffu, nB1, 2);
            nB1 += __shfl_xor_sync(0xffffffffu, nB1, 4);
            if (ac4 == 0) {
                snA[arow] = nA0;  snA[arow + 16] = nA1;
                snB[arow] = nB0;  snB[arow + 16] = nB1;
            }
        }
        __syncthreads();

        if (act) {
            const int mb = m0 + 4 * tx;
#pragma unroll
            for (int i = 0; i < 2; i++) {
                const int q  = q0 + 2 * ty + i;
                const float nq = snA[2 * ty + i];
                float dv[4];
#pragma unroll
                for (int c = 0; c < 4; c++) {
                    float d2 = nq + snB[4 * tx + c] - 2.f * acc[i][c];
                    dv[c] = (q == mb + c) ? 1e6f : sqrtf(fmaxf(d2, 1e-12f));
                }
                *(float4*)&g_D[(size_t)q * N + mb] = make_float4(dv[0], dv[1], dv[2], dv[3]);
                if (ti != tj) {   // symmetric fill (off-diagonal tiles only)
#pragma unroll
                    for (int c = 0; c < 4; c++)
                        g_D[(size_t)(mb + c) * N + q] = dv[c];
                }
            }
        }
    }

    // ======== Grid barrier: monotonic ticket, LOAD-poll (R16-proven) ========
    __syncthreads();
    if (t == 0) {
        __threadfence();
        unsigned tk = atomicAdd(&g_ctr1, 1u);
        unsigned target = (tk / TRI) * TRI + TRI;
        while (*(volatile unsigned*)&g_ctr1 < target)
            __nanosleep(64);
        __threadfence();
    }
    __syncthreads();

    // ======== Phase 2: soft precision (R13-proven, blocks 0..127 only) ========
    if (b < 128) {
        float* sd   = smem;                   // 4 rows x 512
        int*   slab = (int*)(smem + 4 * N);   // 512 labels

        const int lane = t & 31;
        const int w    = t >> 5;
        const int q0b  = b * 4;

        ((float4*)sd)[t] = __ldcg(&((const float4*)(g_D + (size_t)q0b * N))[t]);
        if (t < 128) ((int4*)slab)[t] = ((const int4*)labels)[t];
        __syncthreads();

        const int   qsel = w & 3;
        const int   q    = q0b + qsel;
        const int   lq   = slab[q];
        const float* row = sd + qsel * N;
        const int   jb   = (w >> 2) * 128;

        float num = 0.f;
        int   cnt = 0;
#pragma unroll
        for (int c = 0; c < 4; c++) {
            int j = jb + c * 32 + lane;
            bool f = (j != q) && (slab[j] == lq);
            unsigned bm = __ballot_sync(0xffffffffu, f);
            cnt += __popc(bm);
            while (bm) {                      // ascending j: deterministic
                int bit = __ffs(bm) - 1;
                bm &= bm - 1;
                float dj = row[jb + c * 32 + bit];
                float part = 0.f;
#pragma unroll
                for (int i = 0; i < 16; i++)
                    part += sigmoid_nb((dj - row[lane + 32 * i]) * 100.0f); // 1/T2
#pragma unroll
                for (int o = 16; o; o >>= 1)
                    part += __shfl_xor_sync(0xffffffffu, part, o);
                num += sigmoid_nb(5.0f - part);   // K=5, T1=1
            }
        }
        if (lane == 0) { wnum[w] = num; wcnt[w] = cnt; }
        __syncthreads();

        if (t < 4) {
            float s = wnum[t] + wnum[4 + t] + wnum[8 + t] + wnum[12 + t];
            int   c = wcnt[t] + wcnt[4 + t] + wcnt[8 + t] + wcnt[12 + t];
            g_prec[q0b + t] = s / fminf((float)c, 5.0f);  // 0/0 -> NaN like reference
        }
    }

    // ======== Phase 3: last of all TRI blocks does the fixed-order mean ========
    __syncthreads();
    if (t == 0) {
        __threadfence();
        unsigned tk = atomicAdd(&g_ctr2, 1u);
        s_done = ((tk % TRI) == TRI - 1u) ? 1 : 0;
    }
    __syncthreads();

    if (s_done) {
        __threadfence();
        const int lane = t & 31;
        const int w    = t >> 5;
        float v = __ldcg(&g_prec[t]);         // 512 threads, 512 values
#pragma unroll
        for (int o = 16; o; o >>= 1)
            v += __shfl_xor_sync(0xffffffffu, v, o);
        if (lane == 0) swr[w] = v;
        __syncthreads();
        if (t == 0) {
            float s = 0.f;
#pragma unroll
            for (int i = 0; i < 16; i++) s += swr[i];
            out[0] = 1.0f - s / (float)N;
        }
    }
}

extern "C" void kernel_launch(void* const* d_in, const int* in_sizes, int n_in,
                              void* d_out, int out_size) {
    const float* emb    = (const float*)d_in[0];
    const int*   labels = (const int*)d_in[1];
    k_fused<<<TRI, 512>>>(emb, labels, (float*)d_out);
}